// round 2
// baseline (speedup 1.0000x reference)
#include <cuda_runtime.h>
#include <cstdint>

// Problem dims
#define Bsz   128
#define Tlen  1024
#define Din   64
#define Hd    512
#define NCTA  128
#define NTHR  256
#define UPC   4      // hidden units per CTA (512/128)
#define GCOLS 16     // gate columns per CTA (4 units x 4 gates)

// ---------------- scratch (static __device__, no allocations) ----------------
__device__ float g_xT[Tlen * Din * Bsz];        // 32 MB   x transposed [t][d][b]
__device__ float g_h0[Tlen * Hd * Bsz];         // 256 MB  layer0 outputs [t][u][b]
__device__ float g_h1buf[2][Hd * Bsz];          // 512 KB  layer1 h double buffer
__device__ float g_zero[Hd * Bsz];              // stays zero (bss), never written
__device__ unsigned g_bar_cnt;                  // returns to 0 every barrier
__device__ volatile unsigned g_bar_gen;         // monotonic generation counter

// Replay-safe grid barrier: generation compared relatively, counter self-resets.
__device__ __forceinline__ void grid_sync() {
    __syncthreads();
    if (threadIdx.x == 0) {
        __threadfence();
        unsigned cur = g_bar_gen;                 // read BEFORE arriving (stable until all arrive)
        unsigned arr = atomicAdd(&g_bar_cnt, 1u);
        if (arr == NCTA - 1) {
            atomicExch(&g_bar_cnt, 0u);
            __threadfence();
            atomicAdd((unsigned int*)&g_bar_gen, 1u);
        } else {
            while (*(volatile unsigned*)&g_bar_gen == cur) { __nanosleep(64); }
        }
        __threadfence();
    }
    __syncthreads();
}

__device__ __forceinline__ float sigm(float x) { return 1.0f / (1.0f + __expf(-x)); }

// smem: s_w[16*1024] weight slice (k-major, 16 cols)  +  s_b[16] bias
#define SMEM_FLOATS (16 * 1024 + 32)

extern "C" __global__ void __launch_bounds__(NTHR, 1)
lstm_persistent(const float* __restrict__ x,
                const float* __restrict__ Wih0, const float* __restrict__ Whh0,
                const float* __restrict__ bih0, const float* __restrict__ bhh0,
                const float* __restrict__ Wih1, const float* __restrict__ Whh1,
                const float* __restrict__ bih1, const float* __restrict__ bhh1,
                const float* __restrict__ fc1w, const float* __restrict__ fc1b,
                const float* __restrict__ fc2w, const float* __restrict__ fc2b,
                float* __restrict__ out)
{
    extern __shared__ float smem[];
    float* s_w = smem;
    float* s_b = smem + 16 * 1024;

    const int tid = threadIdx.x;
    const int cta = blockIdx.x;
    const int b   = tid & (Bsz - 1);   // batch column this thread owns
    const int gg  = tid >> 7;          // 0/1: which pair of units
    const int ub  = cta * UPC;         // first global hidden unit of this CTA

    // ---- phase 0: transpose x[b][t][d] -> g_xT[t][d][b] (coalesced writes) ----
    for (int i = cta * NTHR + tid; i < Tlen * Din * Bsz; i += NCTA * NTHR) {
        int bb = i & (Bsz - 1);
        int dd = (i >> 7) & (Din - 1);
        int tt = i >> 13;
        g_xT[i] = x[(bb * Tlen + tt) * Din + dd];
    }
    grid_sync();

    float c0, c1;   // cell state for this thread's (b, unit ub+2*gg+{0,1})

    for (int layer = 0; layer < 2; ++layer) {
        const int Kin = layer ? Hd : Din;
        const float* Wih = layer ? Wih1 : Wih0;
        const float* Whh = layer ? Whh1 : Whh0;
        const float* bih = layer ? bih1 : bih0;
        const float* bhh = layer ? bhh1 : bhh0;

        // ---- stage weight slice into smem: s_w[k*16 + c], c = local_unit*4 + gate ----
        for (int idx = tid; idx < (Kin + Hd) * GCOLS; idx += NTHR) {
            int k  = idx >> 4;
            int c  = idx & 15;
            int lu = c >> 2, q = c & 3;
            int row = q * Hd + ub + lu;
            s_w[idx] = (k < Kin) ? Wih[row * Kin + k] : Whh[row * Hd + (k - Kin)];
        }
        if (tid < GCOLS) {
            int lu = tid >> 2, q = tid & 3;
            int row = q * Hd + ub + lu;
            s_b[tid] = bih[row] + bhh[row];
        }
        __syncthreads();
        c0 = 0.0f; c1 = 0.0f;

        for (int t = 0; t < Tlen; ++t) {
            const float* inA = layer ? (g_h0 + t * (Hd * Bsz))
                                     : (g_xT + t * (Din * Bsz));
            const float* inH = layer ? ((t == 0) ? g_zero : g_h1buf[(t - 1) & 1])
                                     : ((t == 0) ? g_zero : (g_h0 + (t - 1) * (Hd * Bsz)));

            float acc[8];
            #pragma unroll
            for (int j = 0; j < 8; ++j) acc[j] = s_b[8 * gg + j];

            // input-transform part (fused): K = Kin
            const float4* w4a = reinterpret_cast<const float4*>(s_w) + 2 * gg;
            #pragma unroll 8
            for (int k = 0; k < Kin; ++k) {
                float  v  = inA[k * Bsz + b];
                float4 wa = w4a[k * 4];
                float4 wb = w4a[k * 4 + 1];
                acc[0] += v * wa.x; acc[1] += v * wa.y; acc[2] += v * wa.z; acc[3] += v * wa.w;
                acc[4] += v * wb.x; acc[5] += v * wb.y; acc[6] += v * wb.z; acc[7] += v * wb.w;
            }
            // recurrent part: K = 512
            const float4* w4h = reinterpret_cast<const float4*>(s_w + Kin * 16) + 2 * gg;
            #pragma unroll 8
            for (int k = 0; k < Hd; ++k) {
                float  v  = inH[k * Bsz + b];
                float4 wa = w4h[k * 4];
                float4 wb = w4h[k * 4 + 1];
                acc[0] += v * wa.x; acc[1] += v * wa.y; acc[2] += v * wa.z; acc[3] += v * wa.w;
                acc[4] += v * wb.x; acc[5] += v * wb.y; acc[6] += v * wb.z; acc[7] += v * wb.w;
            }

            // gate epilogue (gate order per reference split: i, f, g, o)
            float* outh = layer ? g_h1buf[t & 1] : (g_h0 + t * (Hd * Bsz));
            int gu = ub + 2 * gg;
            {
                float ii = sigm(acc[0]), ff = sigm(acc[1]);
                float gv = tanhf(acc[2]), oo = sigm(acc[3]);
                c0 = ff * c0 + ii * gv;
                outh[gu * Bsz + b] = oo * tanhf(c0);
            }
            {
                float ii = sigm(acc[4]), ff = sigm(acc[5]);
                float gv = tanhf(acc[6]), oo = sigm(acc[7]);
                c1 = ff * c1 + ii * gv;
                outh[(gu + 1) * Bsz + b] = oo * tanhf(c1);
            }
            grid_sync();   // writes of step t visible before step t+1 reads; also
                           // prevents step-(t+1) writers clobbering the buffer step-t readers use
        }
        __syncthreads();   // before smem reuse by next layer
    }

    // ---- FC head: y = (h_last @ fc1^T + b1) @ fc2^T + b2, on CTA 0 ----
    if (cta == 0) {
        // stage fc1w transposed: s_w[k*32 + j]
        for (int idx = tid; idx < 32 * Hd; idx += NTHR) {
            int k = idx >> 5, j = idx & 31;
            s_w[idx] = fc1w[j * Hd + k];
        }
        __syncthreads();
        if (tid < Bsz) {
            const float* hf = g_h1buf[(Tlen - 1) & 1];
            float s[32];
            #pragma unroll
            for (int j = 0; j < 32; ++j) s[j] = 0.0f;
            for (int k = 0; k < Hd; ++k) {
                float v = hf[k * Bsz + tid];
                const float4* w = reinterpret_cast<const float4*>(s_w + k * 32);
                #pragma unroll
                for (int j4 = 0; j4 < 8; ++j4) {
                    float4 ww = w[j4];
                    s[4 * j4 + 0] += v * ww.x;
                    s[4 * j4 + 1] += v * ww.y;
                    s[4 * j4 + 2] += v * ww.z;
                    s[4 * j4 + 3] += v * ww.w;
                }
            }
            float y = fc2b[0];
            #pragma unroll
            for (int j = 0; j < 32; ++j) y += fc2w[j] * (s[j] + fc1b[j]);
            out[tid] = y;
        }
    }
}

extern "C" void kernel_launch(void* const* d_in, const int* in_sizes, int n_in,
                              void* d_out, int out_size)
{
    (void)in_sizes; (void)n_in; (void)out_size;
    const float* x    = (const float*)d_in[0];
    const float* Wih0 = (const float*)d_in[1];
    const float* Whh0 = (const float*)d_in[2];
    const float* bih0 = (const float*)d_in[3];
    const float* bhh0 = (const float*)d_in[4];
    const float* Wih1 = (const float*)d_in[5];
    const float* Whh1 = (const float*)d_in[6];
    const float* bih1 = (const float*)d_in[7];
    const float* bhh1 = (const float*)d_in[8];
    const float* fc1w = (const float*)d_in[9];
    const float* fc1b = (const float*)d_in[10];
    const float* fc2w = (const float*)d_in[11];
    const float* fc2b = (const float*)d_in[12];
    float* out = (float*)d_out;

    size_t smem_bytes = SMEM_FLOATS * sizeof(float);
    cudaFuncSetAttribute(lstm_persistent,
                         cudaFuncAttributeMaxDynamicSharedMemorySize,
                         (int)smem_bytes);
    lstm_persistent<<<NCTA, NTHR, smem_bytes>>>(
        x, Wih0, Whh0, bih0, bhh0, Wih1, Whh1, bih1, bhh1,
        fc1w, fc1b, fc2w, fc2b, out);
}

// round 4
// speedup vs baseline: 2.0726x; 2.0726x over previous
#include <cuda_runtime.h>
#include <cstdint>

#define TLEN 1024
#define BSZ  128
#define DIN  64
#define HD   512
#define RCTA 64          // recurrence CTAs (64 x 32 gate-cols = 2048)
#define RTHR 128

// ---------------- device scratch (static, no allocations) ----------------
__device__ float g_xg[(size_t)TLEN * 64 * 128 * 32];   // 1 GB: [t][cg][thr][32] frag-layout
__device__ float g_h0[(size_t)TLEN * BSZ * HD];        // 256 MB: layer0 h trace [t][b][u]
__device__ float g_h1[2][BSZ * HD];                    // layer1 h double buffer [b][u]
__device__ float g_zero[BSZ * HD];                     // stays zero
__device__ unsigned g_bar_cnt;
__device__ volatile unsigned g_bar_gen;

// ---------------- helpers ----------------
__device__ __forceinline__ uint32_t tf32u(float x) {
    uint32_t u; asm("cvt.rna.tf32.f32 %0, %1;" : "=r"(u) : "f"(x)); return u;
}
__device__ __forceinline__ float tf32r(float x) { return __uint_as_float(tf32u(x)); }

__device__ __forceinline__ void mma8(float d[4], const uint32_t a[4], const uint32_t b[2]) {
    asm volatile("mma.sync.aligned.m16n8k8.row.col.f32.tf32.tf32.f32 "
        "{%0,%1,%2,%3}, {%4,%5,%6,%7}, {%8,%9}, {%0,%1,%2,%3};"
        : "+f"(d[0]), "+f"(d[1]), "+f"(d[2]), "+f"(d[3])
        : "r"(a[0]), "r"(a[1]), "r"(a[2]), "r"(a[3]), "r"(b[0]), "r"(b[1]));
}

__device__ __forceinline__ float sigm(float x) { return 1.0f / (1.0f + __expf(-x)); }

// Replay-safe grid barrier (monotonic generation, counter self-resets).
__device__ __forceinline__ void grid_sync() {
    __syncthreads();
    if (threadIdx.x == 0) {
        __threadfence();
        unsigned cur = g_bar_gen;
        unsigned arr = atomicAdd(&g_bar_cnt, 1u);
        if (arr == RCTA - 1) {
            atomicExch(&g_bar_cnt, 0u);
            __threadfence();
            atomicAdd((unsigned int*)&g_bar_gen, 1u);
        } else {
            while (*(volatile unsigned*)&g_bar_gen == cur) { __nanosleep(32); }
        }
        __threadfence();
    }
    __syncthreads();
}

// =====================================================================
// Transform pass: xg[t, col, b] = sum_k A[t, b, k] * Wih[col, k] + bih + bhh
// Written in the recurrence's per-thread fragment layout.
// Grid (32 colpairs, 128 tgroups), 256 thr. Each block: 64 cols, 8 t's.
// =====================================================================
__global__ void __launch_bounds__(256, 1)
xform(const float* __restrict__ Aptr, int srcmode, size_t t_stride, int row_stride, int Kin,
      const float* __restrict__ Wih, const float* __restrict__ bih,
      const float* __restrict__ bhh)
{
    extern __shared__ float sm[];
    float* Ws = sm;                 // [Kin][72 pad], 64 cols
    float* bs = sm + Kin * 72;      // 64 biases

    const float* A = srcmode ? g_h0 : Aptr;
    const int tid = threadIdx.x, l = tid & 31, wg = tid >> 5;
    const int w4 = wg & 3, cgl = wg >> 2;
    const int cgp = blockIdx.x;
    const int g4 = l >> 2, tq = l & 3;

    for (int i = tid; i < Kin * 64; i += 256) {
        int k = i >> 6, c = i & 63;
        int cl2 = c >> 5, gate = (c >> 3) & 3, u = c & 7;
        int row = gate * HD + (cgp * 2 + cl2) * 8 + u;
        Ws[k * 72 + c] = tf32r(Wih[(size_t)row * Kin + k]);
    }
    if (tid < 64) {
        int cl2 = tid >> 5, gate = (tid >> 3) & 3, u = tid & 7;
        int row = gate * HD + (cgp * 2 + cl2) * 8 + u;
        bs[tid] = bih[row] + bhh[row];
    }
    __syncthreads();

    const int r0 = w4 * 32 + g4;
    const int cg = cgp * 2 + cgl;
    const int nch = Kin >> 3;

    for (int tt = 0; tt < 8; ++tt) {
        const int t = blockIdx.y * 8 + tt;
        const float* ab  = A + (size_t)t * t_stride;
        const float* a00 = ab + (size_t)r0 * row_stride + tq;
        const float* a01 = a00 + (size_t)8  * row_stride;
        const float* a10 = a00 + (size_t)16 * row_stride;
        const float* a11 = a00 + (size_t)24 * row_stride;

        float D[2][4][4];
        #pragma unroll
        for (int m = 0; m < 2; ++m)
            #pragma unroll
            for (int g = 0; g < 4; ++g) {
                float b0 = bs[cgl * 32 + g * 8 + 2 * tq];
                float b1 = bs[cgl * 32 + g * 8 + 2 * tq + 1];
                D[m][g][0] = b0; D[m][g][1] = b1; D[m][g][2] = b0; D[m][g][3] = b1;
            }

        #pragma unroll 4
        for (int kc = 0; kc < nch; ++kc) {
            const int ko = kc * 8;
            uint32_t a0[4] = { tf32u(a00[ko]), tf32u(a01[ko]),
                               tf32u(a00[ko + 4]), tf32u(a01[ko + 4]) };
            uint32_t a1[4] = { tf32u(a10[ko]), tf32u(a11[ko]),
                               tf32u(a10[ko + 4]), tf32u(a11[ko + 4]) };
            const float* wb  = Ws + (size_t)(ko + tq) * 72 + cgl * 32 + g4;
            const float* wb4 = wb + 4 * 72;
            #pragma unroll
            for (int g = 0; g < 4; ++g) {
                uint32_t b[2] = { __float_as_uint(wb[g * 8]), __float_as_uint(wb4[g * 8]) };
                mma8(D[0][g], a0, b);
                mma8(D[1][g], a1, b);
            }
        }

        float4* dst = (float4*)(g_xg + ((((size_t)t * 64 + cg) * 128) + (w4 * 32 + l)) * 32);
        #pragma unroll
        for (int m = 0; m < 2; ++m)
            #pragma unroll
            for (int g = 0; g < 4; ++g)
                dst[m * 4 + g] = make_float4(D[m][g][0], D[m][g][1], D[m][g][2], D[m][g][3]);
    }
}

// =====================================================================
// Recurrence: 64 persistent CTAs, 128 thr; CTA cg owns 32 gate-cols
// (col = gate*8 + unit, units cg*8..cg*8+7). W_hh slice in smem.
// Per step: D = xg-frag; 64 k-chunks mma.sync (A = h from L2); gates.
// =====================================================================
__global__ void __launch_bounds__(RTHR, 1)
rec(int layer, const float* __restrict__ Whh,
    const float* __restrict__ fc1w, const float* __restrict__ fc1b,
    const float* __restrict__ fc2w, const float* __restrict__ fc2b,
    float* __restrict__ out, int do_fc)
{
    extern __shared__ float sm[];
    float* Ws = sm;                  // [512][40 pad], 32 cols

    const int tid = threadIdx.x, l = tid & 31, w = tid >> 5;
    const int g4 = l >> 2, tq = l & 3;
    const int cg = blockIdx.x;

    for (int i = tid; i < HD * 32; i += RTHR) {
        int k = i >> 5, c = i & 31;
        int gate = c >> 3, u = c & 7;
        int row = gate * HD + cg * 8 + u;
        Ws[k * 40 + c] = tf32r(Whh[(size_t)row * HD + k]);
    }
    __syncthreads();

    float cst[8];
    #pragma unroll
    for (int s = 0; s < 8; ++s) cst[s] = 0.0f;
    const int r0 = w * 32 + g4;

    for (int t = 0; t < TLEN; ++t) {
        const float* hp = layer ? (t ? g_h1[(t - 1) & 1] : g_zero)
                                : (t ? g_h0 + (size_t)(t - 1) * (BSZ * HD) : g_zero);
        const float* a00 = hp + (size_t)r0 * HD + tq;
        const float* a01 = a00 + 8 * HD;
        const float* a10 = a00 + 16 * HD;
        const float* a11 = a00 + 24 * HD;

        float D[2][4][4];
        const float4* xp = (const float4*)(g_xg + (((size_t)t * 64 + cg) * 128 + tid) * 32);
        #pragma unroll
        for (int m = 0; m < 2; ++m)
            #pragma unroll
            for (int g = 0; g < 4; ++g) {
                float4 v = xp[m * 4 + g];
                D[m][g][0] = v.x; D[m][g][1] = v.y; D[m][g][2] = v.z; D[m][g][3] = v.w;
            }

        #pragma unroll 4
        for (int kc = 0; kc < 64; ++kc) {
            const int ko = kc * 8;
            // h values were tf32-rounded when written — no cvt needed here
            uint32_t a0[4] = { __float_as_uint(a00[ko]), __float_as_uint(a01[ko]),
                               __float_as_uint(a00[ko + 4]), __float_as_uint(a01[ko + 4]) };
            uint32_t a1[4] = { __float_as_uint(a10[ko]), __float_as_uint(a11[ko]),
                               __float_as_uint(a10[ko + 4]), __float_as_uint(a11[ko + 4]) };
            const float* wb  = Ws + (size_t)(ko + tq) * 40 + g4;
            const float* wb4 = wb + 4 * 40;
            #pragma unroll
            for (int g = 0; g < 4; ++g) {
                uint32_t b[2] = { __float_as_uint(wb[g * 8]), __float_as_uint(wb4[g * 8]) };
                mma8(D[0][g], a0, b);
                mma8(D[1][g], a1, b);
            }
        }

        float* ho = layer ? g_h1[t & 1] : g_h0 + (size_t)t * (BSZ * HD);
        #pragma unroll
        for (int m = 0; m < 2; ++m)
            #pragma unroll
            for (int rr = 0; rr < 2; ++rr) {
                float h2[2];
                #pragma unroll
                for (int j = 0; j < 2; ++j) {
                    int q = rr * 2 + j;
                    float gi = sigm(D[m][0][q]);
                    float gf = sigm(D[m][1][q]);
                    float gv = tanhf(D[m][2][q]);
                    float go = sigm(D[m][3][q]);
                    int s = m * 4 + rr * 2 + j;
                    cst[s] = gf * cst[s] + gi * gv;
                    h2[j] = tf32r(go * tanhf(cst[s]));
                }
                int row = r0 + m * 16 + rr * 8;
                *(float2*)(ho + (size_t)row * HD + cg * 8 + 2 * tq) = make_float2(h2[0], h2[1]);
            }
        grid_sync();
    }

    // ---------------- FC head (layer 1 only, CTA 0) ----------------
    if (do_fc && cg == 0) {
        for (int i = tid; i < HD * 32; i += RTHR) {
            int u = i >> 5, j = i & 31;
            Ws[i] = fc1w[j * HD + u];
        }
        __syncthreads();
        const float* hf = g_h1[(TLEN - 1) & 1];
        float s[32];
        #pragma unroll
        for (int j = 0; j < 32; ++j) s[j] = 0.0f;
        for (int u = 0; u < HD; ++u) {
            float v = hf[(size_t)tid * HD + u];
            const float4* ww = (const float4*)(Ws + u * 32);
            #pragma unroll
            for (int j4 = 0; j4 < 8; ++j4) {
                float4 wv = ww[j4];
                s[4 * j4 + 0] += v * wv.x;
                s[4 * j4 + 1] += v * wv.y;
                s[4 * j4 + 2] += v * wv.z;
                s[4 * j4 + 3] += v * wv.w;
            }
        }
        float y = fc2b[0];
        #pragma unroll
        for (int j = 0; j < 32; ++j) y += fc2w[j] * (s[j] + fc1b[j]);
        out[tid] = y;
    }
}

// =====================================================================
extern "C" void kernel_launch(void* const* d_in, const int* in_sizes, int n_in,
                              void* d_out, int out_size)
{
    (void)in_sizes; (void)n_in; (void)out_size;
    const float* x    = (const float*)d_in[0];
    const float* Wih0 = (const float*)d_in[1];
    const float* Whh0 = (const float*)d_in[2];
    const float* bih0 = (const float*)d_in[3];
    const float* bhh0 = (const float*)d_in[4];
    const float* Wih1 = (const float*)d_in[5];
    const float* Whh1 = (const float*)d_in[6];
    const float* bih1 = (const float*)d_in[7];
    const float* bhh1 = (const float*)d_in[8];
    const float* fc1w = (const float*)d_in[9];
    const float* fc1b = (const float*)d_in[10];
    const float* fc2w = (const float*)d_in[11];
    const float* fc2b = (const float*)d_in[12];
    float* out = (float*)d_out;

    const size_t sm_x0 = (size_t)(DIN * 72 + 64) * 4;
    const size_t sm_x1 = (size_t)(HD * 72 + 64) * 4;
    const size_t sm_r  = (size_t)(HD * 40) * 4;
    cudaFuncSetAttribute(xform, cudaFuncAttributeMaxDynamicSharedMemorySize, (int)sm_x1);
    cudaFuncSetAttribute(rec,   cudaFuncAttributeMaxDynamicSharedMemorySize, (int)sm_r);

    dim3 gx(32, TLEN / 8);
    // layer 0: A = x [b][t][64] -> t_stride=64, row_stride=TLEN*DIN
    xform<<<gx, 256, sm_x0>>>(x, 0, (size_t)DIN, TLEN * DIN, DIN, Wih0, bih0, bhh0);
    rec<<<RCTA, RTHR, sm_r>>>(0, Whh0, fc1w, fc1b, fc2w, fc2b, out, 0);
    // layer 1: A = g_h0 [t][b][512] -> t_stride=BSZ*HD, row_stride=HD
    xform<<<gx, 256, sm_x1>>>(nullptr, 1, (size_t)(BSZ * HD), HD, HD, Wih1, bih1, bhh1);
    rec<<<RCTA, RTHR, sm_r>>>(1, Whh1, fc1w, fc1b, fc2w, fc2b, out, 1);
}